// round 5
// baseline (speedup 1.0000x reference)
#include <cuda_runtime.h>

// ---------------------------------------------------------------------------
// AgentAttention — fp32 baseline
// B=16, C=512, H=W=56 (n=3136), heads=8, hd=64, agent=49, pool=7
// x.reshape(B,n,C) is a raw view: input is a plain (50176,512) row-major matrix.
// ---------------------------------------------------------------------------

#define B_    16
#define C_    512
#define Hh    56
#define Ww    56
#define Nn    3136
#define HEADS 8
#define HD    64
#define AG    49
#define BNr   (B_*Nn)        // 50176 rows
#define SCALE 0.125f         // hd^-0.5

// -------- scratch (allocation-free: __device__ globals) --------------------
__device__ float g_qkv[BNr * 1536];            // q | k | v  (308 MB)
__device__ float g_agent[B_ * AG * C_];        // pooled agent tokens
__device__ float g_bias1[HEADS * AG * Nn];     // resize(an)+ah+aw   [h][a][n]
__device__ float g_bias2[HEADS * Nn * AG];     // resize(na)^T+ha+wa [h][n][a]
__device__ float g_logits[B_ * HEADS * AG * Nn]; // agent logits -> attn (in place)
__device__ float g_agentv[B_ * HEADS * AG * HD];
__device__ float g_attnout[BNr * C_];          // attn out + dwc (proj input)

// ===========================================================================
// SGEMM:  C = A(MxK, row) * W(NxK, row)^T  (+bias), K=512 here.
// 128x128 tile, BK=8, 256 threads, 8x8 per thread.
// mode 0: A = Aext (x),       C = g_qkv   (ldc=1536), W split at `split`
// mode 1: A = g_attnout,      C = Cext    (ldc=512)
// ===========================================================================
#define BM  128
#define BNt 128
#define BK  8

__global__ __launch_bounds__(256) void sgemm_kernel(
    const float* __restrict__ Aext, float* __restrict__ Cext,
    const float* __restrict__ W0, const float* __restrict__ W1,
    const float* __restrict__ bias, int K, int ldc, int split, int mode)
{
    __shared__ float As[BK][BM];
    __shared__ float Bs[BK][BNt];

    const float* A = mode ? g_attnout : Aext;
    float*       C = mode ? Cext      : g_qkv;

    const int tid  = threadIdx.x;
    const int col0 = blockIdx.x * BNt;
    const int row0 = blockIdx.y * BM;

    const float* Bw = (col0 < split) ? (W0 + (size_t)col0 * K)
                                     : (W1 + (size_t)(col0 - split) * K);

    const int lr = tid >> 1;          // 0..127
    const int lc = (tid & 1) << 2;    // 0 or 4
    const float* Ap = A  + (size_t)(row0 + lr) * K + lc;
    const float* Bp = Bw + (size_t)lr * K + lc;

    const int tm = (tid >> 4) << 3;
    const int tn = (tid & 15) << 3;

    float acc[8][8];
#pragma unroll
    for (int i = 0; i < 8; i++)
#pragma unroll
        for (int j = 0; j < 8; j++) acc[i][j] = 0.f;

    for (int k0 = 0; k0 < K; k0 += BK) {
        float4 a4 = *(const float4*)(Ap + k0);
        float4 b4 = *(const float4*)(Bp + k0);
        __syncthreads();
        As[lc + 0][lr] = a4.x; As[lc + 1][lr] = a4.y;
        As[lc + 2][lr] = a4.z; As[lc + 3][lr] = a4.w;
        Bs[lc + 0][lr] = b4.x; Bs[lc + 1][lr] = b4.y;
        Bs[lc + 2][lr] = b4.z; Bs[lc + 3][lr] = b4.w;
        __syncthreads();
#pragma unroll
        for (int kk = 0; kk < BK; kk++) {
            float ar[8], br[8];
            *(float4*)(ar)     = *(const float4*)&As[kk][tm];
            *(float4*)(ar + 4) = *(const float4*)&As[kk][tm + 4];
            *(float4*)(br)     = *(const float4*)&Bs[kk][tn];
            *(float4*)(br + 4) = *(const float4*)&Bs[kk][tn + 4];
#pragma unroll
            for (int i = 0; i < 8; i++)
#pragma unroll
                for (int j = 0; j < 8; j++) acc[i][j] += ar[i] * br[j];
        }
    }

    float bv[8];
#pragma unroll
    for (int j = 0; j < 8; j++) bv[j] = bias ? bias[col0 + tn + j] : 0.f;

#pragma unroll
    for (int i = 0; i < 8; i++) {
        size_t off = (size_t)(row0 + tm + i) * ldc + col0 + tn;
        float4 o0 = make_float4(acc[i][0] + bv[0], acc[i][1] + bv[1],
                                acc[i][2] + bv[2], acc[i][3] + bv[3]);
        float4 o1 = make_float4(acc[i][4] + bv[4], acc[i][5] + bv[5],
                                acc[i][6] + bv[6], acc[i][7] + bv[7]);
        *(float4*)&C[off]     = o0;
        *(float4*)&C[off + 4] = o1;
    }
}

// ===========================================================================
// agent token pooling: mean over 8x8 windows of q (channel-last image view)
// ===========================================================================
__global__ void pool_kernel()
{
    const int ba = blockIdx.x;          // b*49 + a
    const int b = ba / AG, a = ba % AG;
    const int p1 = a / 7, p2 = a % 7;
    for (int c = threadIdx.x; c < C_; c += blockDim.x) {
        float s = 0.f;
        for (int h2 = 0; h2 < 8; h2++)
            for (int w2 = 0; w2 < 8; w2++) {
                int nidx = (p1 * 8 + h2) * Ww + p2 * 8 + w2;
                s += g_qkv[((size_t)(b * Nn + nidx)) * 1536 + c];
            }
        g_agent[(size_t)ba * C_ + c] = s * (1.f / 64.f);
    }
}

// ===========================================================================
// bilinear 7x7 -> 56x56, half-pixel centers, clamp-to-edge
// (identical to jax.image.resize 'bilinear' incl. border renormalization)
// ===========================================================================
__device__ __forceinline__ float bilerp7(const float* t, int y, int x)
{
    float sy = (y + 0.5f) * 0.125f - 0.5f;
    float sx = (x + 0.5f) * 0.125f - 0.5f;
    float fy0 = floorf(sy), fx0 = floorf(sx);
    float wy = sy - fy0, wx = sx - fx0;
    int y0 = (int)fy0, x0 = (int)fx0;
    int y0c = min(max(y0, 0), 6),     y1c = min(max(y0 + 1, 0), 6);
    int x0c = min(max(x0, 0), 6),     x1c = min(max(x0 + 1, 0), 6);
    float v00 = t[y0c * 7 + x0c], v01 = t[y0c * 7 + x1c];
    float v10 = t[y1c * 7 + x0c], v11 = t[y1c * 7 + x1c];
    float top = v00 + wx * (v01 - v00);
    float bot = v10 + wx * (v11 - v10);
    return top + wy * (bot - top);
}

// bias1[h][a][n] = resize(an_bias)[h,a,y,x] + ah_bias[h,a,y] + aw_bias[h,a,x]
__global__ void bias1_kernel(const float* __restrict__ an,
                             const float* __restrict__ ahb,
                             const float* __restrict__ awb)
{
    const int ha = blockIdx.x;           // h*49 + a
    __shared__ float t[49];
    if (threadIdx.x < 49) t[threadIdx.x] = an[ha * 49 + threadIdx.x];
    __syncthreads();
    const float* ah_row = ahb + ha * 56;
    const float* aw_row = awb + ha * 56;
    for (int i = threadIdx.x; i < Nn; i += blockDim.x) {
        int y = i / 56, x = i - y * 56;
        g_bias1[(size_t)ha * Nn + i] = bilerp7(t, y, x) + ah_row[y] + aw_row[x];
    }
}

// bias2[h][n][a] = resize(na_bias)[h,a,y,x] + ha_bias[h,y,a] + wa_bias[h,x,a]
__global__ void bias2_kernel(const float* __restrict__ na,
                             const float* __restrict__ hab,
                             const float* __restrict__ wab)
{
    const int hy = blockIdx.x;           // h*56 + y
    const int h = hy / 56, y = hy - h * 56;
    __shared__ float t[AG * 49];
    for (int i = threadIdx.x; i < AG * 49; i += blockDim.x)
        t[i] = na[h * AG * 49 + i];
    __syncthreads();
    const float* ha_row = hab + (size_t)(h * 56 + y) * AG;
    float* outp = g_bias2 + (size_t)h * Nn * AG + (size_t)y * 56 * AG;
    for (int i = threadIdx.x; i < 56 * AG; i += blockDim.x) {
        int x = i / AG, a = i - x * AG;
        outp[i] = bilerp7(t + a * 49, y, x) + ha_row[a]
                + wab[(size_t)(h * 56 + x) * AG + a];
    }
}

// ===========================================================================
// agent logits: logits[bh][a][n] = scale*ah . k  + bias1[h][a][n]
// grid (49 n-chunks of 64, B*H)
// ===========================================================================
__global__ __launch_bounds__(256) void alogits_kernel()
{
    const int bh = blockIdx.y, b = bh >> 3, h = bh & 7;
    const int n0 = blockIdx.x * 64;
    __shared__ float Ks[64][65];
    __shared__ float ahS[AG * 64];
    const int tid = threadIdx.x;

    for (int i = tid; i < AG * 64; i += 256) {
        int a = i >> 6, d = i & 63;
        ahS[i] = g_agent[(size_t)(b * AG + a) * C_ + h * 64 + d] * SCALE;
    }
    for (int i = tid; i < 64 * 16; i += 256) {
        int nn = i >> 4, d4 = (i & 15) << 2;
        float4 v = *(const float4*)&g_qkv[((size_t)(b * Nn + n0 + nn)) * 1536 + 512 + h * 64 + d4];
        Ks[nn][d4] = v.x; Ks[nn][d4 + 1] = v.y;
        Ks[nn][d4 + 2] = v.z; Ks[nn][d4 + 3] = v.w;
    }
    __syncthreads();

    for (int o = tid; o < AG * 64; o += 256) {
        int a = o >> 6, nn = o & 63;
        float acc = g_bias1[(size_t)(h * AG + a) * Nn + n0 + nn];
        const float* ap = &ahS[a << 6];
#pragma unroll
        for (int d = 0; d < 64; d++) acc += ap[d] * Ks[nn][d];
        g_logits[((size_t)(bh * AG + a)) * Nn + n0 + nn] = acc;
    }
}

// ===========================================================================
// row softmax over n=3136 (in place), one block per (b,h,a) row
// ===========================================================================
__global__ __launch_bounds__(256) void softmax_rows_kernel()
{
    float* p = g_logits + (size_t)blockIdx.x * Nn;
    const int tid = threadIdx.x;
    __shared__ float redm[8], reds[8];

    float m = -1e30f;
    for (int i = tid; i < Nn; i += 256) m = fmaxf(m, p[i]);
#pragma unroll
    for (int o = 16; o; o >>= 1) m = fmaxf(m, __shfl_xor_sync(~0u, m, o));
    if ((tid & 31) == 0) redm[tid >> 5] = m;
    __syncthreads();
    m = redm[0];
#pragma unroll
    for (int w = 1; w < 8; w++) m = fmaxf(m, redm[w]);

    float s = 0.f;
    for (int i = tid; i < Nn; i += 256) s += expf(p[i] - m);
#pragma unroll
    for (int o = 16; o; o >>= 1) s += __shfl_xor_sync(~0u, s, o);
    if ((tid & 31) == 0) reds[tid >> 5] = s;
    __syncthreads();
    s = reds[0];
#pragma unroll
    for (int w = 1; w < 8; w++) s += reds[w];
    float inv = 1.f / s;

    for (int i = tid; i < Nn; i += 256) p[i] = expf(p[i] - m) * inv;
}

// ===========================================================================
// agent_v[bh][a][d] = sum_n attn[bh][a][n] * v[b][n][h*64+d]
// one block per (b,h); stream n in chunks of 64
// ===========================================================================
__global__ __launch_bounds__(256) void agentv_kernel()
{
    const int bh = blockIdx.x, b = bh >> 3, h = bh & 7;
    __shared__ float Vs[64][65];
    __shared__ float Ps[AG * 64];
    const int tid = threadIdx.x;

    float acc[13];
#pragma unroll
    for (int j = 0; j < 13; j++) acc[j] = 0.f;

    for (int n0 = 0; n0 < Nn; n0 += 64) {
        __syncthreads();
        for (int i = tid; i < 64 * 16; i += 256) {
            int nn = i >> 4, d4 = (i & 15) << 2;
            float4 v = *(const float4*)&g_qkv[((size_t)(b * Nn + n0 + nn)) * 1536 + 1024 + h * 64 + d4];
            Vs[nn][d4] = v.x; Vs[nn][d4 + 1] = v.y;
            Vs[nn][d4 + 2] = v.z; Vs[nn][d4 + 3] = v.w;
        }
        for (int i = tid; i < AG * 64; i += 256) {
            int a = i >> 6, nn = i & 63;
            Ps[i] = g_logits[((size_t)(bh * AG + a)) * Nn + n0 + nn];
        }
        __syncthreads();
#pragma unroll
        for (int j = 0; j < 13; j++) {
            int o = tid + j * 256;
            if (o < AG * 64) {
                int a = o >> 6, d = o & 63;
                const float* pp = &Ps[a << 6];
                float s = 0.f;
#pragma unroll 8
                for (int nn = 0; nn < 64; nn++) s += pp[nn] * Vs[nn][d];
                acc[j] += s;
            }
        }
    }
#pragma unroll
    for (int j = 0; j < 13; j++) {
        int o = tid + j * 256;
        if (o < AG * 64) g_agentv[(size_t)bh * AG * 64 + o] = acc[j];
    }
}

// ===========================================================================
// q-side attention, fused: logits -> softmax(49) -> @agent_v -> g_attnout
// grid (49 n-chunks of 64, B*H)
// ===========================================================================
__global__ __launch_bounds__(256) void qattn_kernel()
{
    const int bh = blockIdx.y, b = bh >> 3, h = bh & 7;
    const int n0 = blockIdx.x * 64;
    __shared__ float qS[64][65];       // reused for agent_v after phase 2
    __shared__ float ahS[AG * 64];
    __shared__ float pS[64 * AG];
    const int tid = threadIdx.x;

    for (int i = tid; i < AG * 64; i += 256) {
        int a = i >> 6, d = i & 63;
        ahS[i] = g_agent[(size_t)(b * AG + a) * C_ + h * 64 + d] * SCALE;
    }
    for (int i = tid; i < 64 * 16; i += 256) {
        int nl = i >> 4, d4 = (i & 15) << 2;
        float4 v = *(const float4*)&g_qkv[((size_t)(b * Nn + n0 + nl)) * 1536 + h * 64 + d4];
        qS[nl][d4] = v.x; qS[nl][d4 + 1] = v.y;
        qS[nl][d4 + 2] = v.z; qS[nl][d4 + 3] = v.w;
    }
    __syncthreads();

    // phase 1: logits -> pS[nl][a]
    for (int o = tid; o < AG * 64; o += 256) {
        int a = o >> 6, nl = o & 63;
        float acc = g_bias2[(size_t)h * Nn * AG + (size_t)(n0 + nl) * AG + a];
        const float* ap = &ahS[a << 6];
#pragma unroll
        for (int d = 0; d < 64; d++) acc += ap[d] * qS[nl][d];
        pS[nl * AG + a] = acc;
    }
    __syncthreads();

    // load agent_v into qS's storage (phase-1 reads of qS are done)
    float* avS = &qS[0][0];
    for (int i = tid; i < AG * 64; i += 256)
        avS[i] = g_agentv[(size_t)bh * AG * 64 + i];

    // phase 2: softmax over 49 per n (64 rows)
    if (tid < 64) {
        float* row = &pS[tid * AG];
        float m = row[0];
#pragma unroll
        for (int a = 1; a < AG; a++) m = fmaxf(m, row[a]);
        float s = 0.f;
#pragma unroll
        for (int a = 0; a < AG; a++) { float e = expf(row[a] - m); row[a] = e; s += e; }
        float inv = 1.f / s;
#pragma unroll
        for (int a = 0; a < AG; a++) row[a] *= inv;
    }
    __syncthreads();

    // phase 3: out[nl][d] = sum_a p[a] * av[a][d]
    for (int o = tid; o < 64 * 64; o += 256) {
        int nl = o >> 6, d = o & 63;
        const float* pr = &pS[nl * AG];
        float acc = 0.f;
#pragma unroll
        for (int a = 0; a < AG; a++) acc += pr[a] * avS[a * 64 + d];
        g_attnout[(size_t)(b * Nn + n0 + nl) * C_ + h * 64 + d] = acc;
    }
}

// ===========================================================================
// depthwise 3x3 conv on v (channel-last), accumulate into g_attnout (+bias)
// one block per (b, y), 512 threads = channels
// ===========================================================================
__global__ __launch_bounds__(512) void dwc_kernel(const float* __restrict__ w,
                                                  const float* __restrict__ bias)
{
    const int by = blockIdx.x, b = by / Hh, y = by - b * Hh;
    const int c = threadIdx.x;
    float wr[9];
#pragma unroll
    for (int j = 0; j < 9; j++) wr[j] = w[c * 9 + j];
    const float bv = bias[c];
    const float* vbase = g_qkv + (size_t)b * Nn * 1536 + 1024 + c;
    float* obase = g_attnout + (size_t)b * Nn * C_ + c;

    for (int x = 0; x < Ww; x++) {
        float acc = bv;
#pragma unroll
        for (int ky = -1; ky <= 1; ky++) {
            int yy = y + ky;
            if (yy < 0 || yy >= Hh) continue;
#pragma unroll
            for (int kx = -1; kx <= 1; kx++) {
                int xx = x + kx;
                if (xx < 0 || xx >= Ww) continue;
                acc += vbase[(size_t)(yy * Ww + xx) * 1536] * wr[(ky + 1) * 3 + (kx + 1)];
            }
        }
        obase[(size_t)(y * Ww + x) * C_] += acc;
    }
}

// ===========================================================================
extern "C" void kernel_launch(void* const* d_in, const int* in_sizes, int n_in,
                              void* d_out, int out_size)
{
    const float* x       = (const float*)d_in[0];
    // d_in[1], d_in[2] = H, W (compile-time constants here)
    const float* q_w     = (const float*)d_in[3];
    const float* kv_w    = (const float*)d_in[4];
    const float* proj_w  = (const float*)d_in[5];
    const float* proj_b  = (const float*)d_in[6];
    const float* dwc_w   = (const float*)d_in[7];
    const float* dwc_b   = (const float*)d_in[8];
    const float* an_bias = (const float*)d_in[9];
    const float* na_bias = (const float*)d_in[10];
    const float* ah_bias = (const float*)d_in[11];
    const float* aw_bias = (const float*)d_in[12];
    const float* ha_bias = (const float*)d_in[13];
    const float* wa_bias = (const float*)d_in[14];
    float* out = (float*)d_out;

    // 1. fused QKV GEMM: g_qkv = x @ [q_w; kv_w]^T      (50176 x 1536)
    sgemm_kernel<<<dim3(1536 / BNt, BNr / BM), 256>>>(
        x, nullptr, q_w, kv_w, nullptr, 512, 1536, 512, 0);

    // 2. agent token pooling (8x8 mean)
    pool_kernel<<<B_ * AG, 256>>>();

    // 3. position bias precompute (bilinear resize + additive biases)
    bias1_kernel<<<HEADS * AG, 256>>>(an_bias, ah_bias, aw_bias);
    bias2_kernel<<<HEADS * Hh, 256>>>(na_bias, ha_bias, wa_bias);

    // 4. agent attention: logits, softmax(n), @V
    alogits_kernel<<<dim3(Nn / 64, B_ * HEADS), 256>>>();
    softmax_rows_kernel<<<B_ * HEADS * AG, 256>>>();
    agentv_kernel<<<B_ * HEADS, 256>>>();

    // 5. q attention fused (logits + softmax(49) + @agent_v)
    qattn_kernel<<<dim3(Nn / 64, B_ * HEADS), 256>>>();

    // 6. depthwise conv on v, accumulated into attention output
    dwc_kernel<<<B_ * Hh, 512>>>(dwc_w, dwc_b);

    // 7. projection GEMM + bias -> d_out (raw (B,n,C) == (B,C,H,W) view)
    sgemm_kernel<<<dim3(512 / BNt, BNr / BM), 256>>>(
        nullptr, out, proj_w, proj_w, proj_b, 512, 512, 1 << 30, 1);
}

// round 9
// speedup vs baseline: 1.4880x; 1.4880x over previous
#include <cuda_runtime.h>
#include <cuda_bf16.h>
#include <cstdint>

// ---------------------------------------------------------------------------
// AgentAttention — HMMA (mma.sync bf16) split-precision GEMMs + fp32 attention
// B=16, C=512, H=W=56 (n=3136), heads=8, hd=64, agent=49, pool=7
// NOTE: tcgen05 is unusable here (harness PTX target is compute_103, not
// compute_103a); mma.sync/ldmatrix/cp.async are portable sm_80+ features.
// ---------------------------------------------------------------------------

#define B_    16
#define C_    512
#define Hh    56
#define Ww    56
#define Nn    3136
#define HEADS 8
#define HD    64
#define AG    49
#define BNr   (B_*Nn)        // 50176 rows
#define SCALE 0.125f         // hd^-0.5

// -------- scratch (allocation-free: __device__ globals) --------------------
__device__ float g_qkv[BNr * 1536];              // q | k | v  (fp32)
__device__ float g_agent[B_ * AG * C_];
__device__ float g_bias1[HEADS * AG * Nn];
__device__ float g_bias2[HEADS * Nn * AG];
__device__ float g_logits[B_ * HEADS * AG * Nn];
__device__ float g_agentv[B_ * HEADS * AG * HD];
__device__ float g_attnout[BNr * C_];

// bf16 split buffers: A' = [hi(512) | lo(512)] per row (1024 cols)
__device__ __align__(16) __nv_bfloat16 g_abf[(size_t)BNr * 1024];
// B' = [hi | hi | lo] per row (1536 cols)
__device__ __align__(16) __nv_bfloat16 g_wqkv[1536 * 1536];
__device__ __align__(16) __nv_bfloat16 g_wproj[512 * 1536];

// ===========================================================================
// PTX helpers (portable: sm_80+ only)
// ===========================================================================
__device__ __forceinline__ uint32_t smem_u32(const void* p) {
    uint32_t a;
    asm("{ .reg .u64 t; cvta.to.shared.u64 t, %1; cvt.u32.u64 %0, t; }"
        : "=r"(a) : "l"(p));
    return a;
}

#define CP16(dst, src) \
    asm volatile("cp.async.cg.shared.global [%0], [%1], 16;" \
                 :: "r"(dst), "l"(src) : "memory")
#define CP_COMMIT() asm volatile("cp.async.commit_group;" ::: "memory")
#define CP_WAIT(n)  asm volatile("cp.async.wait_group %0;" :: "n"(n) : "memory")

#define LDSM_X4(r, addr) \
    asm volatile("ldmatrix.sync.aligned.m8n8.x4.shared.b16 {%0,%1,%2,%3}, [%4];" \
                 : "=r"((r)[0]), "=r"((r)[1]), "=r"((r)[2]), "=r"((r)[3]) \
                 : "r"(addr))

#define MMA16816(c, a, b0, b1) \
    asm volatile("mma.sync.aligned.m16n8k16.row.col.f32.bf16.bf16.f32 " \
                 "{%0,%1,%2,%3}, {%4,%5,%6,%7}, {%8,%9}, {%0,%1,%2,%3};" \
                 : "+f"((c)[0]), "+f"((c)[1]), "+f"((c)[2]), "+f"((c)[3]) \
                 : "r"((a)[0]), "r"((a)[1]), "r"((a)[2]), "r"((a)[3]), \
                   "r"(b0), "r"(b1))

// ===========================================================================
// HMMA GEMM: C[m][n] = sum_k' A'[m][map(k')] * B'[n][k']  (+bias)
// CTA 128x128, K'=1536 in 48 chunks of 32, double-buffered cp.async.
// A' has 1024 cols [hi|lo]; chunk c<32 -> A col c*32 ; c>=32 -> (c-32)*32
// (hi reread for the hi*lo term).  B' has 1536 cols [hi|hi|lo].
// 8 warps, warp tile 32(M)x64(N), atoms m16n8k16.
// ===========================================================================
#define SPAD 40   // bf16 row stride in smem (80B: 16B-aligned, ldmatrix conflict-free)

__global__ __launch_bounds__(256) void mma_gemm_kernel(
    float* __restrict__ Cext, const float* __restrict__ bias, int ldc, int wsel)
{
    __shared__ __nv_bfloat16 As[2][128][SPAD];
    __shared__ __nv_bfloat16 Bs[2][128][SPAD];

    const int tid = threadIdx.x, lane = tid & 31, wid = tid >> 5;
    float* C = Cext ? Cext : g_qkv;
    const __nv_bfloat16* Bw = wsel ? g_wproj : g_wqkv;
    const int col0 = blockIdx.x * 128, row0 = blockIdx.y * 128;

    const int wm = (wid & 3) * 32;    // warp M offset in CTA tile
    const int wn = (wid >> 2) * 64;   // warp N offset

    float acc[2][8][4];
#pragma unroll
    for (int im = 0; im < 2; im++)
#pragma unroll
        for (int in = 0; in < 8; in++)
#pragma unroll
            for (int j = 0; j < 4; j++) acc[im][in][j] = 0.f;

    // loader indices: thread handles rows r_ld and r_ld+64, col seg s_ld
    const int r_ld = tid >> 2;
    const int s_ld = (tid & 3) * 8;

    // ldmatrix source addresses (per warp, fixed row/col-in-tile patterns)
    const int arow = wm + (lane & 15);
    const int acol_off = (lane >> 4) << 3;               // 0 or 8
    const int brow = wn + ((lane >> 4) << 3) + (lane & 7);
    const int bcol_off = ((lane >> 3) & 1) << 3;         // 0 or 8

#define ISSUE_CHUNK(buf, c) do { \
    int kb0 = (c) * 32; \
    int ka0 = ((c) < 32) ? kb0 : kb0 - 1024; \
    const __nv_bfloat16* ap = g_abf + (size_t)(row0 + r_ld) * 1024 + ka0 + s_ld; \
    const __nv_bfloat16* bp = Bw    + (size_t)(col0 + r_ld) * 1536 + kb0 + s_ld; \
    uint32_t da = smem_u32(&As[buf][r_ld][s_ld]); \
    uint32_t db = smem_u32(&Bs[buf][r_ld][s_ld]); \
    CP16(da, ap); \
    CP16(db, bp); \
    CP16(da + 64 * (SPAD * 2), ap + (size_t)64 * 1024); \
    CP16(db + 64 * (SPAD * 2), bp + (size_t)64 * 1536); \
} while (0)

    ISSUE_CHUNK(0, 0);
    CP_COMMIT();

    int buf = 0;
    for (int c = 0; c < 48; c++) {
        if (c + 1 < 48) {
            ISSUE_CHUNK(buf ^ 1, c + 1);
            CP_COMMIT();
            CP_WAIT(1);
        } else {
            CP_WAIT(0);
        }
        __syncthreads();

#pragma unroll
        for (int ks = 0; ks < 2; ks++) {
            const int k0 = ks * 16;
            uint32_t a[2][4], b[4][4];
#pragma unroll
            for (int im = 0; im < 2; im++)
                LDSM_X4(a[im], smem_u32(&As[buf][arow + im * 16][k0 + acol_off]));
#pragma unroll
            for (int p = 0; p < 4; p++)
                LDSM_X4(b[p], smem_u32(&Bs[buf][brow + p * 16][k0 + bcol_off]));
#pragma unroll
            for (int im = 0; im < 2; im++)
#pragma unroll
                for (int in = 0; in < 8; in++) {
                    const uint32_t* bp2 = &b[in >> 1][(in & 1) * 2];
                    MMA16816(acc[im][in], a[im], bp2[0], bp2[1]);
                }
        }
        __syncthreads();
        buf ^= 1;
    }

    // epilogue: c-frag rows = base + lane/4 (+8), cols = base + 2*(lane%4)
#pragma unroll
    for (int im = 0; im < 2; im++) {
        const int row = row0 + wm + im * 16 + (lane >> 2);
#pragma unroll
        for (int in = 0; in < 8; in++) {
            const int col = col0 + wn + in * 8 + ((lane & 3) << 1);
            float b0 = bias ? bias[col] : 0.f;
            float b1 = bias ? bias[col + 1] : 0.f;
            *(float2*)&C[(size_t)row * ldc + col] =
                make_float2(acc[im][in][0] + b0, acc[im][in][1] + b1);
            *(float2*)&C[(size_t)(row + 8) * ldc + col] =
                make_float2(acc[im][in][2] + b0, acc[im][in][3] + b1);
        }
    }
#undef ISSUE_CHUNK
}

// ===========================================================================
// fp32 -> bf16 hi/lo split conversions
// ===========================================================================
__global__ __launch_bounds__(256) void cvtA_kernel(const float* __restrict__ xext,
                                                   int useAttn)
{
    const float* src = useAttn ? g_attnout : xext;
    size_t i = (size_t)blockIdx.x * 256 + threadIdx.x;   // handles 4 floats
    size_t r = i >> 7;
    int c4 = (int)(i & 127) << 2;
    float4 v = *(const float4*)(src + r * 512 + c4);
    __nv_bfloat162 h01 = __floats2bfloat162_rn(v.x, v.y);
    __nv_bfloat162 h23 = __floats2bfloat162_rn(v.z, v.w);
    __nv_bfloat162 l01 = __floats2bfloat162_rn(v.x - __bfloat162float(h01.x),
                                               v.y - __bfloat162float(h01.y));
    __nv_bfloat162 l23 = __floats2bfloat162_rn(v.z - __bfloat162float(h23.x),
                                               v.w - __bfloat162float(h23.y));
    __nv_bfloat162* dh = (__nv_bfloat162*)(g_abf + r * 1024 + c4);
    __nv_bfloat162* dl = (__nv_bfloat162*)(g_abf + r * 1024 + 512 + c4);
    dh[0] = h01; dh[1] = h23;
    dl[0] = l01; dl[1] = l23;
}

__global__ __launch_bounds__(256) void cvtW_kernel(const float* __restrict__ w0,
                                                   const float* __restrict__ w1,
                                                   int nsplit, int wsel)
{
    __nv_bfloat16* dst = wsel ? g_wproj : g_wqkv;
    size_t i = (size_t)blockIdx.x * 256 + threadIdx.x;
    size_t n = i >> 7;
    int c4 = (int)(i & 127) << 2;
    const float* srow = (n < (size_t)nsplit) ? (w0 + n * 512)
                                             : (w1 + (n - nsplit) * 512);
    float4 v = *(const float4*)(srow + c4);
    __nv_bfloat162 h01 = __floats2bfloat162_rn(v.x, v.y);
    __nv_bfloat162 h23 = __floats2bfloat162_rn(v.z, v.w);
    __nv_bfloat162 l01 = __floats2bfloat162_rn(v.x - __bfloat162float(h01.x),
                                               v.y - __bfloat162float(h01.y));
    __nv_bfloat162 l23 = __floats2bfloat162_rn(v.z - __bfloat162float(h23.x),
                                               v.w - __bfloat162float(h23.y));
    __nv_bfloat162* d0 = (__nv_bfloat162*)(dst + n * 1536 + c4);          // hi
    __nv_bfloat162* d1 = (__nv_bfloat162*)(dst + n * 1536 + 512 + c4);    // hi
    __nv_bfloat162* d2 = (__nv_bfloat162*)(dst + n * 1536 + 1024 + c4);   // lo
    d0[0] = h01; d0[1] = h23;
    d1[0] = h01; d1[1] = h23;
    d2[0] = l01; d2[1] = l23;
}

// ===========================================================================
// agent token pooling: mean over 8x8 windows of q
// ===========================================================================
__global__ void pool_kernel()
{
    const int ba = blockIdx.x;
    const int b = ba / AG, a = ba % AG;
    const int p1 = a / 7, p2 = a % 7;
    for (int c = threadIdx.x; c < C_; c += blockDim.x) {
        float s = 0.f;
        for (int h2 = 0; h2 < 8; h2++)
            for (int w2 = 0; w2 < 8; w2++) {
                int nidx = (p1 * 8 + h2) * Ww + p2 * 8 + w2;
                s += g_qkv[((size_t)(b * Nn + nidx)) * 1536 + c];
            }
        g_agent[(size_t)ba * C_ + c] = s * (1.f / 64.f);
    }
}

// ===========================================================================
// bilinear 7x7 -> 56x56 (half-pixel, clamp-to-edge)
// ===========================================================================
__device__ __forceinline__ float bilerp7(const float* t, int y, int x)
{
    float sy = (y + 0.5f) * 0.125f - 0.5f;
    float sx = (x + 0.5f) * 0.125f - 0.5f;
    float fy0 = floorf(sy), fx0 = floorf(sx);
    float wy = sy - fy0, wx = sx - fx0;
    int y0 = (int)fy0, x0 = (int)fx0;
    int y0c = min(max(y0, 0), 6),     y1c = min(max(y0 + 1, 0), 6);
    int x0c = min(max(x0, 0), 6),     x1c = min(max(x0 + 1, 0), 6);
    float v00 = t[y0c * 7 + x0c], v01 = t[y0c * 7 + x1c];
    float v10 = t[y1c * 7 + x0c], v11 = t[y1c * 7 + x1c];
    float top = v00 + wx * (v01 - v00);
    float bot = v10 + wx * (v11 - v10);
    return top + wy * (bot - top);
}

__global__ void bias1_kernel(const float* __restrict__ an,
                             const float* __restrict__ ahb,
                             const float* __restrict__ awb)
{
    const int ha = blockIdx.x;
    __shared__ float t[49];
    if (threadIdx.x < 49) t[threadIdx.x] = an[ha * 49 + threadIdx.x];
    __syncthreads();
    const float* ah_row = ahb + ha * 56;
    const float* aw_row = awb + ha * 56;
    for (int i = threadIdx.x; i < Nn; i += blockDim.x) {
        int y = i / 56, x = i - y * 56;
        g_bias1[(size_t)ha * Nn + i] = bilerp7(t, y, x) + ah_row[y] + aw_row[x];
    }
}

__global__ void bias2_kernel(const float* __restrict__ na,
                             const float* __restrict__ hab,
                             const float* __restrict__ wab)
{
    const int hy = blockIdx.x;
    const int h = hy / 56, y = hy - h * 56;
    __shared__ float t[AG * 49];
    for (int i = threadIdx.x; i < AG * 49; i += blockDim.x)
        t[i] = na[h * AG * 49 + i];
    __syncthreads();
    const float* ha_row = hab + (size_t)(h * 56 + y) * AG;
    float* outp = g_bias2 + (size_t)h * Nn * AG + (size_t)y * 56 * AG;
    for (int i = threadIdx.x; i < 56 * AG; i += blockDim.x) {
        int x = i / AG, a = i - x * AG;
        outp[i] = bilerp7(t + a * 49, y, x) + ha_row[a]
                + wab[(size_t)(h * 56 + x) * AG + a];
    }
}

// ===========================================================================
// agent logits
// ===========================================================================
__global__ __launch_bounds__(256) void alogits_kernel()
{
    const int bh = blockIdx.y, b = bh >> 3, h = bh & 7;
    const int n0 = blockIdx.x * 64;
    __shared__ float Ks[64][65];
    __shared__ float ahS[AG * 64];
    const int tid = threadIdx.x;

    for (int i = tid; i < AG * 64; i += 256) {
        int a = i >> 6, d = i & 63;
        ahS[i] = g_agent[(size_t)(b * AG + a) * C_ + h * 64 + d] * SCALE;
    }
    for (int i = tid; i < 64 * 16; i += 256) {
        int nn = i >> 4, d4 = (i & 15) << 2;
        float4 v = *(const float4*)&g_qkv[((size_t)(b * Nn + n0 + nn)) * 1536 + 512 + h * 64 + d4];
        Ks[nn][d4] = v.x; Ks[nn][d4 + 1] = v.y;
        Ks[nn][d4 + 2] = v.z; Ks[nn][d4 + 3] = v.w;
    }
    __syncthreads();

    for (int o = tid; o < AG * 64; o += 256) {
        int a = o >> 6, nn = o & 63;
        float acc = g_bias1[(size_t)(h * AG + a) * Nn + n0 + nn];
        const float* ap = &ahS[a << 6];
#pragma unroll
        for (int d = 0; d < 64; d++) acc += ap[d] * Ks[nn][d];
        g_logits[((size_t)(bh * AG + a)) * Nn + n0 + nn] = acc;
    }
}

// ===========================================================================
// row softmax over n=3136
// ===========================================================================
__global__ __launch_bounds__(256) void softmax_rows_kernel()
{
    float* p = g_logits + (size_t)blockIdx.x * Nn;
    const int tid = threadIdx.x;
    __shared__ float redm[8], reds[8];

    float m = -1e30f;
    for (int i = tid; i < Nn; i += 256) m = fmaxf(m, p[i]);
#pragma unroll
    for (int o = 16; o; o >>= 1) m = fmaxf(m, __shfl_xor_sync(~0u, m, o));
    if ((tid & 31) == 0) redm[tid >> 5] = m;
    __syncthreads();
    m = redm[0];
#pragma unroll
    for (int w = 1; w < 8; w++) m = fmaxf(m, redm[w]);

    float s = 0.f;
    for (int i = tid; i < Nn; i += 256) s += expf(p[i] - m);
#pragma unroll
    for (int o = 16; o; o >>= 1) s += __shfl_xor_sync(~0u, s, o);
    if ((tid & 31) == 0) reds[tid >> 5] = s;
    __syncthreads();
    s = reds[0];
#pragma unroll
    for (int w = 1; w < 8; w++) s += reds[w];
    float inv = 1.f / s;

    for (int i = tid; i < Nn; i += 256) p[i] = expf(p[i] - m) * inv;
}

// ===========================================================================
// agent_v
// ===========================================================================
__global__ __launch_bounds__(256) void agentv_kernel()
{
    const int bh = blockIdx.x, b = bh >> 3, h = bh & 7;
    __shared__ float Vs[64][65];
    __shared__ float Ps[AG * 64];
    const int tid = threadIdx.x;

    float acc[13];
#pragma unroll
    for (int j = 0; j < 13; j++) acc[j] = 0.f;

    for (int n0 = 0; n0 < Nn; n0 += 64) {
        __syncthreads();
        for (int i = tid; i < 64 * 16; i += 256) {
            int nn = i >> 4, d4 = (i & 15) << 2;
            float4 v = *(const float4*)&g_qkv[((size_t)(b * Nn + n0 + nn)) * 1536 + 1024 + h * 64 + d4];
            Vs[nn][d4] = v.x; Vs[nn][d4 + 1] = v.y;
            Vs[nn][d4 + 2] = v.z; Vs[nn][d4 + 3] = v.w;
        }
        for (int i = tid; i < AG * 64; i += 256) {
            int a = i >> 6, nn = i & 63;
            Ps[i] = g_logits[((size_t)(bh * AG + a)) * Nn + n0 + nn];
        }
        __syncthreads();
#pragma unroll
        for (int j = 0; j < 13; j++) {
            int o = tid + j * 256;
            if (o < AG * 64) {
                int a = o >> 6, d = o & 63;
                const float* pp = &Ps[a << 6];
                float s = 0.f;
#pragma unroll 8
                for (int nn = 0; nn < 64; nn++) s += pp[nn] * Vs[nn][d];
                acc[j] += s;
            }
        }
    }
#pragma unroll
    for (int j = 0; j < 13; j++) {
        int o = tid + j * 256;
        if (o < AG * 64) g_agentv[(size_t)bh * AG * 64 + o] = acc[j];
    }
}

// ===========================================================================
// q-side attention, fused
// ===========================================================================
__global__ __launch_bounds__(256) void qattn_kernel()
{
    const int bh = blockIdx.y, b = bh >> 3, h = bh & 7;
    const int n0 = blockIdx.x * 64;
    __shared__ float qS[64][65];
    __shared__ float ahS[AG * 64];
    __shared__ float pS[64 * AG];
    const int tid = threadIdx.x;

    for (int i = tid; i < AG * 64; i += 256) {
        int a = i >> 6, d = i & 63;
        ahS[i] = g_agent[(size_t)(b * AG + a) * C_ + h * 64 + d] * SCALE;
    }
    for (int i = tid; i < 64 * 16; i += 256) {
        int nl = i >> 4, d4 = (i & 15) << 2;
        float4 v = *(const float4*)&g_qkv[((size_t)(b * Nn + n0 + nl)) * 1536 + h * 64 + d4];
        qS[nl][d4] = v.x; qS[nl][d4 + 1] = v.y;
        qS[nl][d4 + 2] = v.z; qS[nl][d4 + 3] = v.w;
    }
    __syncthreads();

    for (int o = tid; o < AG * 64; o += 256) {
        int a = o >> 6, nl = o & 63;
        float acc = g_bias2[(size_t)h * Nn * AG + (size_t)(n0 + nl) * AG + a];
        const float* ap = &ahS[a << 6];
#pragma unroll
        for (int d = 0; d < 64; d++) acc += ap[d] * qS[nl][d];
        pS[nl * AG + a] = acc;
    }
    __syncthreads();

    float* avS = &qS[0][0];
    for (int i = tid; i < AG * 64; i += 256)
        avS[i] = g_agentv[(size_t)bh * AG * 64 + i];

    if (tid < 64) {
        float* row = &pS[tid * AG];
        float m = row[0];
#pragma unroll
        for (int a = 1; a < AG; a++) m = fmaxf(m, row[a]);
        float s = 0.f;
#pragma unroll
        for (int a = 0; a < AG; a++) { float e = expf(row[a] - m); row[a] = e; s += e; }
        float inv = 1.f / s;
#pragma unroll
        for (int a = 0; a < AG; a++) row[a] *= inv;
    }
    __syncthreads();

    for (int o = tid; o < 64 * 64; o += 256) {
        int nl = o >> 6, d = o & 63;
        const float* pr = &pS[nl * AG];
        float acc = 0.f;
#pragma unroll
        for (int a = 0; a < AG; a++) acc += pr[a] * avS[a * 64 + d];
        g_attnout[(size_t)(b * Nn + n0 + nl) * C_ + h * 64 + d] = acc;
    }
}

// ===========================================================================
// depthwise 3x3 conv on v, accumulate into g_attnout (+bias)
// ===========================================================================
__global__ __launch_bounds__(512) void dwc_kernel(const float* __restrict__ w,
                                                  const float* __restrict__ bias)
{
    const int by = blockIdx.x, b = by / Hh, y = by - b * Hh;
    const int c = threadIdx.x;
    float wr[9];
#pragma unroll
    for (int j = 0; j < 9; j++) wr[j] = w[c * 9 + j];
    const float bv = bias[c];
    const float* vbase = g_qkv + (size_t)b * Nn * 1536 + 1024 + c;
    float* obase = g_attnout + (size_t)b * Nn * C_ + c;

    for (int x = 0; x < Ww; x++) {
        float acc = bv;
#pragma unroll
        for (int ky = -1; ky <= 1; ky++) {
            int yy = y + ky;
            if (yy < 0 || yy >= Hh) continue;
#pragma unroll
            for (int kx = -1; kx <= 1; kx++) {
                int xx = x + kx;
                if (xx < 0 || xx >= Ww) continue;
                acc += vbase[(size_t)(yy * Ww + xx) * 1536] * wr[(ky + 1) * 3 + (kx + 1)];
            }
        }
        obase[(size_t)(y * Ww + x) * C_] += acc;
    }
}

// ===========================================================================
extern "C" void kernel_launch(void* const* d_in, const int* in_sizes, int n_in,
                              void* d_out, int out_size)
{
    const float* x       = (const float*)d_in[0];
    const float* q_w     = (const float*)d_in[3];
    const float* kv_w    = (const float*)d_in[4];
    const float* proj_w  = (const float*)d_in[5];
    const float* proj_b  = (const float*)d_in[6];
    const float* dwc_w   = (const float*)d_in[7];
    const float* dwc_b   = (const float*)d_in[8];
    const float* an_bias = (const float*)d_in[9];
    const float* na_bias = (const float*)d_in[10];
    const float* ah_bias = (const float*)d_in[11];
    const float* aw_bias = (const float*)d_in[12];
    const float* ha_bias = (const float*)d_in[13];
    const float* wa_bias = (const float*)d_in[14];
    float* out = (float*)d_out;

    // 1. bf16 hi/lo conversions: x -> g_abf ; weights -> g_wqkv / g_wproj
    cvtA_kernel<<<(BNr * 512 / 4) / 256, 256>>>(x, 0);
    cvtW_kernel<<<(1536 * 512 / 4) / 256, 256>>>(q_w, kv_w, 512, 0);
    cvtW_kernel<<<(512 * 512 / 4) / 256, 256>>>(proj_w, proj_w, 512, 1);

    // 2. fused QKV GEMM (HMMA bf16-split): g_qkv = x @ [q_w; kv_w]^T
    mma_gemm_kernel<<<dim3(12, 392), 256>>>(nullptr, nullptr, 1536, 0);

    // 3. agent token pooling
    pool_kernel<<<B_ * AG, 256>>>();

    // 4. position biases
    bias1_kernel<<<HEADS * AG, 256>>>(an_bias, ah_bias, aw_bias);
    bias2_kernel<<<HEADS * Hh, 256>>>(na_bias, ha_bias, wa_bias);

    // 5. agent attention
    alogits_kernel<<<dim3(Nn / 64, B_ * HEADS), 256>>>();
    softmax_rows_kernel<<<B_ * HEADS * AG, 256>>>();
    agentv_kernel<<<B_ * HEADS, 256>>>();

    // 6. q attention fused
    qattn_kernel<<<dim3(Nn / 64, B_ * HEADS), 256>>>();

    // 7. depthwise conv accumulate
    dwc_kernel<<<B_ * Hh, 512>>>(dwc_w, dwc_b);

    // 8. proj GEMM (HMMA bf16-split): out = attnout @ proj_w^T + b
    cvtA_kernel<<<(BNr * 512 / 4) / 256, 256>>>(nullptr, 1);
    mma_gemm_kernel<<<dim3(4, 392), 256>>>(out, proj_b, 512, 1);
}